// round 5
// baseline (speedup 1.0000x reference)
#include <cuda_runtime.h>
#include <cuda_fp16.h>
#include <cstdint>

// Problem constants (fixed shapes)
#define NNODES 10000
#define NEDGES 640000
#define CIN    128
#define COUT   128
#define HDIM   256
#define BN_EPS 1e-5f

// ---------------------------------------------------------------------------
// Scratch (__device__ globals; no allocation allowed)
// ---------------------------------------------------------------------------
__device__ __half g_ABh[NNODES * 512];  // fp16: [n][0:256]=A' (dst term), [n][256:512]=B (src term)
__device__ float  g_Wc[CIN * 512];      // BN-folded combined weight
__device__ float  g_dv[512];            // combined bias
__device__ __half g_W2h[COUT * HDIM];   // W2 transposed [n][k], fp16
__device__ int    g_is64;
__device__ int    g_src[NEDGES];
__device__ int    g_dst[NEDGES];
// dst-sorted edge arrays + sort workspace
__device__ int    g_ssrc[NEDGES];
__device__ int    g_sdst[NEDGES];
__device__ int    g_cnt[NNODES];
__device__ int    g_cur[NNODES];

// ---------------------------------------------------------------------------
// fp16 mma m16n8k16, fp32 accumulate
// ---------------------------------------------------------------------------
__device__ __forceinline__ void mma_f16(float& c0, float& c1, float& c2, float& c3,
                                        uint32_t a0, uint32_t a1, uint32_t a2, uint32_t a3,
                                        uint32_t b0, uint32_t b1) {
    asm volatile(
        "mma.sync.aligned.m16n8k16.row.col.f32.f16.f16.f32 "
        "{%0,%1,%2,%3}, {%4,%5,%6,%7}, {%8,%9}, {%0,%1,%2,%3};\n"
        : "+f"(c0), "+f"(c1), "+f"(c2), "+f"(c3)
        : "r"(a0), "r"(a1), "r"(a2), "r"(a3), "r"(b0), "r"(b1));
}

__device__ __forceinline__ void ldsm_x4(uint32_t& r0, uint32_t& r1, uint32_t& r2, uint32_t& r3,
                                        uint32_t addr) {
    asm volatile("ldmatrix.sync.aligned.m8n8.x4.shared.b16 {%0,%1,%2,%3}, [%4];"
                 : "=r"(r0), "=r"(r1), "=r"(r2), "=r"(r3) : "r"(addr));
}

// ---------------------------------------------------------------------------
// Kernel A: detect edge_index dtype (int64 -> odd 32-bit words all zero)
// ---------------------------------------------------------------------------
__global__ void detect_kernel(const int* __restrict__ w) {
    __shared__ int acc;
    if (threadIdx.x == 0) acc = 0;
    __syncthreads();
    int v = 0;
    for (int i = threadIdx.x; i < 4096; i += blockDim.x) v |= w[2 * i + 1];
    atomicOr(&acc, v);
    __syncthreads();
    if (threadIdx.x == 0) g_is64 = (acc == 0) ? 1 : 0;
}

// ---------------------------------------------------------------------------
// Kernel B: extract src/dst as int32 (clamped); also zero histogram bins
// ---------------------------------------------------------------------------
__global__ void extract_kernel(const int* __restrict__ w) {
    int i = blockIdx.x * blockDim.x + threadIdx.x;
    if (i < NNODES) g_cnt[i] = 0;
    if (i >= NEDGES) return;
    int s, d;
    if (g_is64) {
        s = w[2 * i];
        d = w[2 * (NEDGES + i)];
    } else {
        s = w[i];
        d = w[NEDGES + i];
    }
    g_src[i] = min(max(s, 0), NNODES - 1);
    g_dst[i] = min(max(d, 0), NNODES - 1);
}

// ---------------------------------------------------------------------------
// Counting sort by dst: histogram -> scan -> scatter
// ---------------------------------------------------------------------------
__global__ void hist_kernel() {
    int i = blockIdx.x * blockDim.x + threadIdx.x;
    if (i < NEDGES) atomicAdd(&g_cnt[g_dst[i]], 1);
}

__global__ __launch_bounds__(1024) void scan_kernel() {
    __shared__ int part[1024];
    int t = threadIdx.x;
    const int PER = (NNODES + 1023) / 1024;   // 10
    int base = t * PER;
    int loc[PER];
    int s = 0;
    #pragma unroll
    for (int i = 0; i < PER; ++i) {
        int b = base + i;
        loc[i] = s;
        if (b < NNODES) s += g_cnt[b];
    }
    part[t] = s;
    __syncthreads();
    for (int off = 1; off < 1024; off <<= 1) {
        int v = (t >= off) ? part[t - off] : 0;
        __syncthreads();
        part[t] += v;
        __syncthreads();
    }
    int pre = (t == 0) ? 0 : part[t - 1];
    #pragma unroll
    for (int i = 0; i < PER; ++i) {
        int b = base + i;
        if (b < NNODES) g_cur[b] = pre + loc[i];
    }
}

__global__ void scatter_kernel() {
    int i = blockIdx.x * blockDim.x + threadIdx.x;
    if (i >= NEDGES) return;
    int d = g_dst[i];
    int pos = atomicAdd(&g_cur[d], 1);
    g_sdst[pos] = d;
    g_ssrc[pos] = g_src[i];
}

// ---------------------------------------------------------------------------
// Kernel 0: prep — fold BN into W1, build combined weight/bias, W2^T fp16
// ---------------------------------------------------------------------------
__global__ void prep_kernel(const float* __restrict__ gamma, const float* __restrict__ beta,
                            const float* __restrict__ mean, const float* __restrict__ var,
                            const float* __restrict__ W1, const float* __restrict__ b1,
                            const float* __restrict__ W2) {
    __shared__ float s_sh[CIN], t_sh[CIN];
    int j = threadIdx.x;  // 0..511
    if (j < CIN) {
        float s = gamma[j] * rsqrtf(var[j] + BN_EPS);
        s_sh[j] = s;
        t_sh[j] = beta[j] - mean[j] * s;
    }
    __syncthreads();

    float acc = 0.f;
    #pragma unroll 4
    for (int k = 0; k < CIN; ++k) {
        float wc;
        if (j < HDIM) wc = W1[k * HDIM + j] - W1[(k + CIN) * HDIM + j];   // W1top - W1bot
        else          wc = W1[(k + CIN) * HDIM + (j - HDIM)];             // W1bot
        g_Wc[k * 512 + j] = s_sh[k] * wc;
        acc += t_sh[k] * wc;
    }
    g_dv[j] = acc + ((j < HDIM) ? b1[j] : 0.f);

    for (int idx = j; idx < COUT * HDIM; idx += 512) {
        int n = idx >> 8, k = idx & 255;
        g_W2h[idx] = __float2half_rn(W2[k * COUT + n]);
    }
}

// ---------------------------------------------------------------------------
// Kernel 1: zero output
// ---------------------------------------------------------------------------
__global__ void zero_kernel(float* __restrict__ out, int n) {
    int i = blockIdx.x * blockDim.x + threadIdx.x;
    if (i < n) out[i] = 0.f;
}

// ---------------------------------------------------------------------------
// Kernel 2: node GEMM  AB[10000,512] = x[10000,128] @ g_Wc[128,512] + g_dv
// ---------------------------------------------------------------------------
__global__ __launch_bounds__(256) void gemm_nodes_kernel(const float* __restrict__ x) {
    __shared__ float As[16][64];
    __shared__ float Bs[16][64];
    int tid = threadIdx.x;
    int m0 = blockIdx.x * 64, n0 = blockIdx.y * 64;
    int tx = tid & 15, ty = tid >> 4;

    int lr = tid >> 2;
    int lc = (tid & 3) * 4;
    int br = tid >> 4;
    int bc = (tid & 15) * 4;

    float acc[4][4];
    #pragma unroll
    for (int i = 0; i < 4; ++i)
        #pragma unroll
        for (int jq = 0; jq < 4; ++jq) acc[i][jq] = 0.f;

    for (int k0 = 0; k0 < CIN; k0 += 16) {
        float4 av = make_float4(0.f, 0.f, 0.f, 0.f);
        int row = m0 + lr;
        if (row < NNODES) av = *(const float4*)(x + row * CIN + k0 + lc);
        As[lc + 0][lr] = av.x; As[lc + 1][lr] = av.y;
        As[lc + 2][lr] = av.z; As[lc + 3][lr] = av.w;

        float4 bv = *(const float4*)(g_Wc + (k0 + br) * 512 + n0 + bc);
        *(float4*)&Bs[br][bc] = bv;
        __syncthreads();

        #pragma unroll
        for (int k = 0; k < 16; ++k) {
            float4 a = *(const float4*)&As[k][ty * 4];
            float4 b = *(const float4*)&Bs[k][tx * 4];
            float ar[4] = {a.x, a.y, a.z, a.w};
            float bw[4] = {b.x, b.y, b.z, b.w};
            #pragma unroll
            for (int i = 0; i < 4; ++i)
                #pragma unroll
                for (int jq = 0; jq < 4; ++jq)
                    acc[i][jq] = fmaf(ar[i], bw[jq], acc[i][jq]);
        }
        __syncthreads();
    }

    float4 dv4 = *(const float4*)(g_dv + n0 + tx * 4);
    #pragma unroll
    for (int i = 0; i < 4; ++i) {
        int row = m0 + ty * 4 + i;
        if (row < NNODES) {
            __half2 h0 = __floats2half2_rn(acc[i][0] + dv4.x, acc[i][1] + dv4.y);
            __half2 h1 = __floats2half2_rn(acc[i][2] + dv4.z, acc[i][3] + dv4.w);
            uint2 o;
            o.x = *(uint32_t*)&h0;
            o.y = *(uint32_t*)&h1;
            *(uint2*)&g_ABh[row * 512 + n0 + tx * 4] = o;
        }
    }
}

// ---------------------------------------------------------------------------
// Kernel 3: persistent edge kernel. Edges sorted by dst -> segmented smem max
// reduction, then 1 atomic per (segment, col) instead of per (edge, col).
// ---------------------------------------------------------------------------
#define TILE_E 64
#define KS 264                      // half stride per h row (132 words; %32==4 conflict-free)
#define NS 132                      // float stride of out_s rows (same bytes as KS halves)
#define NTILES (NEDGES / TILE_E)    // 10000

#define SMEM_W2_HALVES (COUT * KS)    // 33792 halves
#define SMEM_H_HALVES  (TILE_E * KS)  // 16896 halves (overlaid by out_s: 64x132 f32)
#define SMEM_BYTES ((SMEM_W2_HALVES + SMEM_H_HALVES) * 2 + COUT * 4 + 2 * TILE_E * 4)

__global__ __launch_bounds__(256, 2) void edge_kernel(const float* __restrict__ b2,
                                                      int* __restrict__ outI) {
    extern __shared__ __half smem[];
    __half* W2_s = smem;                          // [128][KS]
    __half* h_s  = W2_s + SMEM_W2_HALVES;         // [64][KS]  (stage 1/2)
    float*  out_s = (float*)h_s;                  // [64][NS]  (epilogue overlay)
    float*  b2_s = (float*)(h_s + SMEM_H_HALVES); // [128]
    int*    dst_s = (int*)(b2_s + COUT);          // [64]
    int*    src_s = dst_s + TILE_E;               // [64]

    const int tid  = threadIdx.x;
    const int lane = tid & 31;
    const int w    = tid >> 5;
    const int wm   = w & 1;
    const int wn   = w >> 1;
    const int g    = lane >> 2;
    const int tg   = lane & 3;

    for (int idx = tid; idx < COUT * HDIM / 2; idx += 256) {
        int n = idx >> 7, kw = idx & 127;
        *(uint32_t*)&W2_s[n * KS + 2 * kw] = ((const uint32_t*)g_W2h)[idx];
    }
    if (tid < COUT) b2_s[tid] = b2[tid];

    const uint32_t h_addr  = (uint32_t)__cvta_generic_to_shared(h_s);
    const uint32_t w2_addr = (uint32_t)__cvta_generic_to_shared(W2_s);
    const int mat = lane >> 3, r8 = lane & 7;
    uint32_t aBase[2], bBase[2];
    #pragma unroll
    for (int mt = 0; mt < 2; ++mt) {
        int row = wm * 32 + mt * 16 + (mat & 1) * 8 + r8;
        aBase[mt] = h_addr + (row * KS + (mat >> 1) * 8) * 2;
    }
    #pragma unroll
    for (int p = 0; p < 2; ++p) {
        int n = wn * 32 + p * 16 + (mat >> 1) * 8 + r8;
        bBase[p] = w2_addr + (n * KS + (mat & 1) * 8) * 2;
    }

    const int rsel = tid >> 6;
    const int c4   = (tid & 63) * 4;
    const int rcol  = tid & 127;        // reduction column
    const int rrow0 = (tid >> 7) * 32;  // reduction row block

    for (int tile = blockIdx.x; tile < NTILES; tile += gridDim.x) {
        __syncthreads();

        if (tid < TILE_E) {
            int e = tile * TILE_E + tid;
            src_s[tid] = g_ssrc[e];
            dst_s[tid] = g_sdst[e];
        }
        __syncthreads();

        // Stage 1: fp16 gather + relu -> h_s
        const __half2 z2 = __float2half2_rn(0.f);
        #pragma unroll 8
        for (int m0 = 0; m0 < TILE_E; m0 += 4) {
            int row = m0 + rsel;
            int d = dst_s[row], s = src_s[row];
            uint2 ua = *(const uint2*)&g_ABh[d * 512 + c4];
            uint2 ub = *(const uint2*)&g_ABh[s * 512 + 256 + c4];
            __half2 h0 = __hmax2(__hadd2(*(__half2*)&ua.x, *(__half2*)&ub.x), z2);
            __half2 h1 = __hmax2(__hadd2(*(__half2*)&ua.y, *(__half2*)&ub.y), z2);
            uint2 o;
            o.x = *(uint32_t*)&h0;
            o.y = *(uint32_t*)&h1;
            *(uint2*)&h_s[row * KS + c4] = o;
        }
        __syncthreads();

        // Stage 2: fp16 mma [64x256] @ [256x128]
        float acc[2][4][4];
        #pragma unroll
        for (int mt = 0; mt < 2; ++mt)
            #pragma unroll
            for (int nt = 0; nt < 4; ++nt)
                #pragma unroll
                for (int i = 0; i < 4; ++i) acc[mt][nt][i] = 0.f;

        #pragma unroll 4
        for (int ks = 0; ks < HDIM / 16; ++ks) {
            uint32_t kb = ks * 32;
            uint32_t a[2][4];
            #pragma unroll
            for (int mt = 0; mt < 2; ++mt)
                ldsm_x4(a[mt][0], a[mt][1], a[mt][2], a[mt][3], aBase[mt] + kb);
            uint32_t b[4][2];
            ldsm_x4(b[0][0], b[0][1], b[1][0], b[1][1], bBase[0] + kb);
            ldsm_x4(b[2][0], b[2][1], b[3][0], b[3][1], bBase[1] + kb);
            #pragma unroll
            for (int mt = 0; mt < 2; ++mt)
                #pragma unroll
                for (int nt = 0; nt < 4; ++nt)
                    mma_f16(acc[mt][nt][0], acc[mt][nt][1], acc[mt][nt][2], acc[mt][nt][3],
                            a[mt][0], a[mt][1], a[mt][2], a[mt][3],
                            b[nt][0], b[nt][1]);
        }
        __syncthreads();   // all h_s reads done before overlay write

        // Epilogue A: dump fragments to smem (out_s overlays h_s)
        #pragma unroll
        for (int mt = 0; mt < 2; ++mt) {
            #pragma unroll
            for (int nt = 0; nt < 4; ++nt) {
                #pragma unroll
                for (int i = 0; i < 4; ++i) {
                    int rowm = wm * 32 + mt * 16 + g + ((i >> 1) * 8);
                    int col  = wn * 32 + nt * 8 + tg * 2 + (i & 1);
                    out_s[rowm * NS + col] = acc[mt][nt][i];
                }
            }
        }
        __syncthreads();

        // Epilogue B: segmented column-max over sorted rows, one atomic/segment
        {
            const float b2c = b2_s[rcol];
            float run = -1e30f;
            int prev_d = dst_s[rrow0];
            #pragma unroll 8
            for (int r = rrow0; r < rrow0 + 32; ++r) {
                int d = dst_s[r];
                if (d != prev_d) {
                    float v = run + b2c;
                    if (v > 0.f) atomicMax(outI + prev_d * COUT + rcol, __float_as_int(v));
                    run = -1e30f;
                    prev_d = d;
                }
                run = fmaxf(run, out_s[r * NS + rcol]);
            }
            float v = run + b2c;
            if (v > 0.f) atomicMax(outI + prev_d * COUT + rcol, __float_as_int(v));
        }
    }
}

// ---------------------------------------------------------------------------
// Launch
// ---------------------------------------------------------------------------
extern "C" void kernel_launch(void* const* d_in, const int* in_sizes, int n_in,
                              void* d_out, int out_size) {
    const float* x        = (const float*)d_in[0];
    const int*   eiw      = (const int*)d_in[1];
    const float* bn_gamma = (const float*)d_in[2];
    const float* bn_beta  = (const float*)d_in[3];
    const float* bn_mean  = (const float*)d_in[4];
    const float* bn_var   = (const float*)d_in[5];
    const float* W1       = (const float*)d_in[6];
    const float* b1       = (const float*)d_in[7];
    const float* W2       = (const float*)d_in[8];
    const float* b2       = (const float*)d_in[9];
    float* out = (float*)d_out;

    cudaFuncSetAttribute(edge_kernel, cudaFuncAttributeMaxDynamicSharedMemorySize, SMEM_BYTES);

    detect_kernel<<<1, 256>>>(eiw);
    extract_kernel<<<(NEDGES + 255) / 256, 256>>>(eiw);
    hist_kernel<<<(NEDGES + 255) / 256, 256>>>();
    scan_kernel<<<1, 1024>>>();
    scatter_kernel<<<(NEDGES + 255) / 256, 256>>>();
    prep_kernel<<<1, 512>>>(bn_gamma, bn_beta, bn_mean, bn_var, W1, b1, W2);
    zero_kernel<<<(NNODES * COUT + 511) / 512, 512>>>(out, NNODES * COUT);
    dim3 g1((NNODES + 63) / 64, 512 / 64);
    gemm_nodes_kernel<<<g1, 256>>>(x);
    edge_kernel<<<304, 256, SMEM_BYTES>>>(b2, (int*)d_out);
}

// round 7
// speedup vs baseline: 1.3066x; 1.3066x over previous
#include <cuda_runtime.h>
#include <cuda_fp16.h>
#include <cstdint>

// Problem constants (fixed shapes)
#define NNODES 10000
#define NEDGES 640000
#define CIN    128
#define COUT   128
#define HDIM   256
#define BN_EPS 1e-5f

// ---------------------------------------------------------------------------
// Scratch (__device__ globals; no allocation allowed)
// ---------------------------------------------------------------------------
__device__ __align__(16) __half g_ABh[NNODES * 512];  // [n][0:256]=A' (dst), [n][256:512]=B (src)
__device__ __align__(16) __half g_W2h[COUT * HDIM];   // W2^T [n][k], fp16
__device__ int    g_is64;
__device__ int    g_src[NEDGES];
__device__ int    g_dst[NEDGES];

// ---------------------------------------------------------------------------
// fp16 mma m16n8k16, fp32 accumulate
// ---------------------------------------------------------------------------
__device__ __forceinline__ void mma_f16(float& c0, float& c1, float& c2, float& c3,
                                        uint32_t a0, uint32_t a1, uint32_t a2, uint32_t a3,
                                        uint32_t b0, uint32_t b1) {
    asm volatile(
        "mma.sync.aligned.m16n8k16.row.col.f32.f16.f16.f32 "
        "{%0,%1,%2,%3}, {%4,%5,%6,%7}, {%8,%9}, {%0,%1,%2,%3};\n"
        : "+f"(c0), "+f"(c1), "+f"(c2), "+f"(c3)
        : "r"(a0), "r"(a1), "r"(a2), "r"(a3), "r"(b0), "r"(b1));
}

__device__ __forceinline__ void ldsm_x4(uint32_t& r0, uint32_t& r1, uint32_t& r2, uint32_t& r3,
                                        uint32_t addr) {
    asm volatile("ldmatrix.sync.aligned.m8n8.x4.shared.b16 {%0,%1,%2,%3}, [%4];"
                 : "=r"(r0), "=r"(r1), "=r"(r2), "=r"(r3) : "r"(addr));
}

// ---------------------------------------------------------------------------
// Launch #1: detect edge_index dtype (int64 -> odd 32-bit words all zero)
// ---------------------------------------------------------------------------
__global__ void detect_kernel(const int* __restrict__ w) {
    __shared__ int acc;
    if (threadIdx.x == 0) acc = 0;
    __syncthreads();
    int v = 0;
    for (int i = threadIdx.x; i < 4096; i += blockDim.x) v |= w[2 * i + 1];
    atomicOr(&acc, v);
    __syncthreads();
    if (threadIdx.x == 0) g_is64 = (acc == 0) ? 1 : 0;
}

// ---------------------------------------------------------------------------
// Launch #2: extract src/dst as int32 (clamped)
// ---------------------------------------------------------------------------
__global__ void extract_kernel(const int* __restrict__ w) {
    int i = blockIdx.x * blockDim.x + threadIdx.x;
    if (i >= NEDGES) return;
    int s, d;
    if (g_is64) {
        s = w[2 * i];
        d = w[2 * (NEDGES + i)];
    } else {
        s = w[i];
        d = w[NEDGES + i];
    }
    g_src[i] = min(max(s, 0), NNODES - 1);
    g_dst[i] = min(max(d, 0), NNODES - 1);
}

// ---------------------------------------------------------------------------
// Launch #3: zero output (vectorized)
// ---------------------------------------------------------------------------
__global__ void zero_kernel(float4* __restrict__ out, int n4) {
    int i = blockIdx.x * blockDim.x + threadIdx.x;
    if (i < n4) out[i] = make_float4(0.f, 0.f, 0.f, 0.f);
}

// ---------------------------------------------------------------------------
// Launch #4: W2 transpose to [n][k] fp16
// ---------------------------------------------------------------------------
__global__ void prep_w2t(const float* __restrict__ W2) {
    int idx = blockIdx.x * 256 + threadIdx.x;
    if (idx < COUT * HDIM) {
        int n = idx >> 8, k = idx & 255;
        g_W2h[idx] = __float2half_rn(W2[k * COUT + n]);
    }
}

// ---------------------------------------------------------------------------
// Launch #5: fused prep + node GEMM.
// Each block derives its own BN-folded 128x64 weight slice + bias from
// W1/BN params in smem, then computes AB[m0:m0+64, n0:n0+64] and stores fp16.
// ---------------------------------------------------------------------------
__global__ __launch_bounds__(256) void gemm_fused_kernel(
    const float* __restrict__ x,
    const float* __restrict__ gamma, const float* __restrict__ beta,
    const float* __restrict__ mean, const float* __restrict__ var,
    const float* __restrict__ W1, const float* __restrict__ b1) {
    __shared__ float s_sh[CIN], t_sh[CIN];
    __shared__ float Ws[CIN * 64];     // scaled weight slice [k][64]
    __shared__ float dvp[4 * 64];
    __shared__ float dv_s[64];
    __shared__ float As[16][64];

    int tid = threadIdx.x;
    int m0 = blockIdx.x * 64, n0 = blockIdx.y * 64;

    if (tid < CIN) {
        float s = gamma[tid] * rsqrtf(var[tid] + BN_EPS);
        s_sh[tid] = s;
        t_sh[tid] = beta[tid] - mean[tid] * s;
    }
    __syncthreads();

    // Build weight slice + bias partials
    {
        int jj = tid & 63;
        int kg = tid >> 6;              // 0..3
        int j = n0 + jj;
        float dacc = 0.f;
        #pragma unroll 4
        for (int k = kg * 32; k < kg * 32 + 32; ++k) {
            float wc;
            if (j < HDIM) wc = W1[k * HDIM + j] - W1[(k + CIN) * HDIM + j];
            else          wc = W1[(k + CIN) * HDIM + (j - HDIM)];
            Ws[k * 64 + jj] = s_sh[k] * wc;
            dacc += t_sh[k] * wc;
        }
        dvp[kg * 64 + jj] = dacc;
    }
    __syncthreads();
    if (tid < 64) {
        int j = n0 + tid;
        dv_s[tid] = dvp[tid] + dvp[64 + tid] + dvp[128 + tid] + dvp[192 + tid]
                  + ((j < HDIM) ? b1[j] : 0.f);
    }
    __syncthreads();

    int tx = tid & 15, ty = tid >> 4;
    int lr = tid >> 2;
    int lc = (tid & 3) * 4;

    float acc[4][4];
    #pragma unroll
    for (int i = 0; i < 4; ++i)
        #pragma unroll
        for (int jq = 0; jq < 4; ++jq) acc[i][jq] = 0.f;

    for (int k0 = 0; k0 < CIN; k0 += 16) {
        float4 av = make_float4(0.f, 0.f, 0.f, 0.f);
        int row = m0 + lr;
        if (row < NNODES) av = *(const float4*)(x + row * CIN + k0 + lc);
        As[lc + 0][lr] = av.x; As[lc + 1][lr] = av.y;
        As[lc + 2][lr] = av.z; As[lc + 3][lr] = av.w;
        __syncthreads();

        #pragma unroll
        for (int k = 0; k < 16; ++k) {
            float4 a = *(const float4*)&As[k][ty * 4];
            float4 b = *(const float4*)&Ws[(k0 + k) * 64 + tx * 4];
            float ar[4] = {a.x, a.y, a.z, a.w};
            float bw[4] = {b.x, b.y, b.z, b.w};
            #pragma unroll
            for (int i = 0; i < 4; ++i)
                #pragma unroll
                for (int jq = 0; jq < 4; ++jq)
                    acc[i][jq] = fmaf(ar[i], bw[jq], acc[i][jq]);
        }
        __syncthreads();
    }

    float4 dv4 = *(const float4*)&dv_s[tx * 4];
    #pragma unroll
    for (int i = 0; i < 4; ++i) {
        int row = m0 + ty * 4 + i;
        if (row < NNODES) {
            __half2 h0 = __floats2half2_rn(acc[i][0] + dv4.x, acc[i][1] + dv4.y);
            __half2 h1 = __floats2half2_rn(acc[i][2] + dv4.z, acc[i][3] + dv4.w);
            uint2 o;
            o.x = *(uint32_t*)&h0;
            o.y = *(uint32_t*)&h1;
            *(uint2*)&g_ABh[row * 512 + n0 + tx * 4] = o;
        }
    }
}

// ---------------------------------------------------------------------------
// Launch #6: persistent edge kernel (fp16 gather + ldmatrix + fp16 mma)
// ---------------------------------------------------------------------------
#define TILE_E 64
#define KS 264                      // half stride per row (%32==8 halves pattern; conflict-free)
#define NTILES (NEDGES / TILE_E)    // 10000

#define SMEM_W2_HALVES (COUT * KS)    // 33792 halves = 67584 B
#define SMEM_H_HALVES  (TILE_E * KS)  // 16896 halves = 33792 B
#define SMEM_BYTES ((SMEM_W2_HALVES + SMEM_H_HALVES) * 2 + COUT * 4)

__global__ __launch_bounds__(256, 2) void edge_kernel(const float* __restrict__ b2,
                                                      int* __restrict__ outI) {
    extern __shared__ __half smem[];
    __half* W2_s = smem;                          // [128][KS]
    __half* h_s  = W2_s + SMEM_W2_HALVES;         // [64][KS]
    float*  b2_s = (float*)(h_s + SMEM_H_HALVES); // [128]

    const int tid  = threadIdx.x;
    const int lane = tid & 31;
    const int w    = tid >> 5;
    const int wm   = w & 1;
    const int wn   = w >> 1;
    const int g    = lane >> 2;
    const int tg   = lane & 3;

    // Load W2^T into smem (128-bit)
    for (int idx = tid; idx < COUT * HDIM / 8; idx += 256) {
        int n = idx >> 5, kc = (idx & 31) * 8;
        *(uint4*)&W2_s[n * KS + kc] = *(const uint4*)&g_W2h[n * HDIM + kc];
    }
    if (tid < COUT) b2_s[tid] = b2[tid];
    __syncthreads();

    // ldmatrix per-lane base addresses
    const uint32_t h_addr  = (uint32_t)__cvta_generic_to_shared(h_s);
    const uint32_t w2_addr = (uint32_t)__cvta_generic_to_shared(W2_s);
    const int mat = lane >> 3, r8 = lane & 7;
    uint32_t aBase[2], bBase[2];
    #pragma unroll
    for (int mt = 0; mt < 2; ++mt) {
        int row = wm * 32 + mt * 16 + (mat & 1) * 8 + r8;
        aBase[mt] = h_addr + (row * KS + (mat >> 1) * 8) * 2;
    }
    #pragma unroll
    for (int p = 0; p < 2; ++p) {
        int n = wn * 32 + p * 16 + (mat >> 1) * 8 + r8;
        bBase[p] = w2_addr + (n * KS + (mat & 1) * 8) * 2;
    }

    const int kc8 = lane * 8;   // gather: halves offset (8 per lane, 32 lanes = 256)

    for (int tile = blockIdx.x; tile < NTILES; tile += gridDim.x) {
        const int ebase = tile * TILE_E;

        // Stage 1: gather + relu -> h_s. Warp = one row per pass, 8 passes.
        const __half2 z2 = __float2half2_rn(0.f);
        #pragma unroll
        for (int pass = 0; pass < 8; ++pass) {
            int row = pass * 8 + w;
            int d = __ldg(&g_dst[ebase + row]);
            int s = __ldg(&g_src[ebase + row]);
            uint4 ua = *(const uint4*)&g_ABh[d * 512 + kc8];
            uint4 ub = *(const uint4*)&g_ABh[s * 512 + 256 + kc8];
            uint4 o;
            __half2 h;
            h = __hmax2(__hadd2(*(__half2*)&ua.x, *(__half2*)&ub.x), z2); o.x = *(uint32_t*)&h;
            h = __hmax2(__hadd2(*(__half2*)&ua.y, *(__half2*)&ub.y), z2); o.y = *(uint32_t*)&h;
            h = __hmax2(__hadd2(*(__half2*)&ua.z, *(__half2*)&ub.z), z2); o.z = *(uint32_t*)&h;
            h = __hmax2(__hadd2(*(__half2*)&ua.w, *(__half2*)&ub.w), z2); o.w = *(uint32_t*)&h;
            *(uint4*)&h_s[row * KS + kc8] = o;
        }
        __syncthreads();

        // Stage 2: fp16 mma [64x256] @ [256x128]
        float acc[2][4][4];
        #pragma unroll
        for (int mt = 0; mt < 2; ++mt)
            #pragma unroll
            for (int nt = 0; nt < 4; ++nt)
                #pragma unroll
                for (int i = 0; i < 4; ++i) acc[mt][nt][i] = 0.f;

        #pragma unroll 4
        for (int ks = 0; ks < HDIM / 16; ++ks) {
            uint32_t kb = ks * 32;
            uint32_t a[2][4];
            #pragma unroll
            for (int mt = 0; mt < 2; ++mt)
                ldsm_x4(a[mt][0], a[mt][1], a[mt][2], a[mt][3], aBase[mt] + kb);
            uint32_t b[4][2];
            ldsm_x4(b[0][0], b[0][1], b[1][0], b[1][1], bBase[0] + kb);
            ldsm_x4(b[2][0], b[2][1], b[3][0], b[3][1], bBase[1] + kb);
            #pragma unroll
            for (int mt = 0; mt < 2; ++mt)
                #pragma unroll
                for (int nt = 0; nt < 4; ++nt)
                    mma_f16(acc[mt][nt][0], acc[mt][nt][1], acc[mt][nt][2], acc[mt][nt][3],
                            a[mt][0], a[mt][1], a[mt][2], a[mt][3],
                            b[nt][0], b[nt][1]);
        }
        __syncthreads();   // h_s reads complete before next tile's gather writes

        // Epilogue: +b2, predicated positive-only int atomicMax (no smem dep)
        int drow[2][2];
        #pragma unroll
        for (int mt = 0; mt < 2; ++mt)
            #pragma unroll
            for (int r = 0; r < 2; ++r)
                drow[mt][r] = __ldg(&g_dst[ebase + wm * 32 + mt * 16 + g + r * 8]);

        #pragma unroll
        for (int mt = 0; mt < 2; ++mt) {
            #pragma unroll
            for (int nt = 0; nt < 4; ++nt) {
                #pragma unroll
                for (int i = 0; i < 4; ++i) {
                    int col = wn * 32 + nt * 8 + tg * 2 + (i & 1);
                    float v = acc[mt][nt][i] + b2_s[col];
                    if (v > 0.f) {
                        atomicMax(outI + drow[mt][i >> 1] * COUT + col, __float_as_int(v));
                    }
                }
            }
        }
    }
}

// ---------------------------------------------------------------------------
// Launch — exactly 6 kernels; edge_kernel is #6 so ncu (-s 5 -c 1) captures it
// ---------------------------------------------------------------------------
extern "C" void kernel_launch(void* const* d_in, const int* in_sizes, int n_in,
                              void* d_out, int out_size) {
    const float* x        = (const float*)d_in[0];
    const int*   eiw      = (const int*)d_in[1];
    const float* bn_gamma = (const float*)d_in[2];
    const float* bn_beta  = (const float*)d_in[3];
    const float* bn_mean  = (const float*)d_in[4];
    const float* bn_var   = (const float*)d_in[5];
    const float* W1       = (const float*)d_in[6];
    const float* b1       = (const float*)d_in[7];
    const float* W2       = (const float*)d_in[8];
    const float* b2       = (const float*)d_in[9];

    cudaFuncSetAttribute(edge_kernel, cudaFuncAttributeMaxDynamicSharedMemorySize, SMEM_BYTES);

    detect_kernel<<<1, 256>>>(eiw);                                            // 1
    extract_kernel<<<(NEDGES + 255) / 256, 256>>>(eiw);                        // 2
    zero_kernel<<<(NNODES * COUT / 4 + 255) / 256, 256>>>((float4*)d_out,
                                                          NNODES * COUT / 4);  // 3
    prep_w2t<<<128, 256>>>(W2);                                                // 4
    dim3 g1((NNODES + 63) / 64, 512 / 64);
    gemm_fused_kernel<<<g1, 256>>>(x, bn_gamma, bn_beta, bn_mean, bn_var, W1, b1); // 5
    edge_kernel<<<296, 256, SMEM_BYTES>>>(b2, (int*)d_out);                    // 6
}

// round 8
// speedup vs baseline: 1.4146x; 1.0827x over previous
#include <cuda_runtime.h>
#include <cuda_fp16.h>
#include <cstdint>

// Problem constants (fixed shapes)
#define NNODES 10000
#define NEDGES 640000
#define CIN    128
#define COUT   128
#define HDIM   256
#define BN_EPS 1e-5f

// ---------------------------------------------------------------------------
// Scratch (__device__ globals; no allocation allowed)
// ---------------------------------------------------------------------------
__device__ __align__(16) __half g_ABh[NNODES * 512];  // [n][0:256]=A' (dst), [n][256:512]=B (src)
__device__ __align__(16) __half g_W2h[COUT * HDIM];   // W2^T [n][k], fp16
__device__ int    g_is64;
__device__ int    g_src[NEDGES];
__device__ int    g_dst[NEDGES];

// ---------------------------------------------------------------------------
// fp16 mma m16n8k16 (fp32 accumulate) + ldmatrix helpers
// ---------------------------------------------------------------------------
__device__ __forceinline__ void mma_f16(float& c0, float& c1, float& c2, float& c3,
                                        uint32_t a0, uint32_t a1, uint32_t a2, uint32_t a3,
                                        uint32_t b0, uint32_t b1) {
    asm volatile(
        "mma.sync.aligned.m16n8k16.row.col.f32.f16.f16.f32 "
        "{%0,%1,%2,%3}, {%4,%5,%6,%7}, {%8,%9}, {%0,%1,%2,%3};\n"
        : "+f"(c0), "+f"(c1), "+f"(c2), "+f"(c3)
        : "r"(a0), "r"(a1), "r"(a2), "r"(a3), "r"(b0), "r"(b1));
}

__device__ __forceinline__ void ldsm_x4(uint32_t& r0, uint32_t& r1, uint32_t& r2, uint32_t& r3,
                                        uint32_t addr) {
    asm volatile("ldmatrix.sync.aligned.m8n8.x4.shared.b16 {%0,%1,%2,%3}, [%4];"
                 : "=r"(r0), "=r"(r1), "=r"(r2), "=r"(r3) : "r"(addr));
}

// ---------------------------------------------------------------------------
// Launch #1: detect edge_index dtype (int64 -> odd 32-bit words all zero)
// ---------------------------------------------------------------------------
__global__ void detect_kernel(const int* __restrict__ w) {
    __shared__ int acc;
    if (threadIdx.x == 0) acc = 0;
    __syncthreads();
    int v = 0;
    for (int i = threadIdx.x; i < 4096; i += blockDim.x) v |= w[2 * i + 1];
    atomicOr(&acc, v);
    __syncthreads();
    if (threadIdx.x == 0) g_is64 = (acc == 0) ? 1 : 0;
}

// ---------------------------------------------------------------------------
// Launch #2: extract src/dst as int32 (clamped)
// ---------------------------------------------------------------------------
__global__ void extract_kernel(const int* __restrict__ w) {
    int i = blockIdx.x * blockDim.x + threadIdx.x;
    if (i >= NEDGES) return;
    int s, d;
    if (g_is64) {
        s = w[2 * i];
        d = w[2 * (NEDGES + i)];
    } else {
        s = w[i];
        d = w[NEDGES + i];
    }
    g_src[i] = min(max(s, 0), NNODES - 1);
    g_dst[i] = min(max(d, 0), NNODES - 1);
}

// ---------------------------------------------------------------------------
// Launch #3: zero output (vectorized)
// ---------------------------------------------------------------------------
__global__ void zero_kernel(float4* __restrict__ out, int n4) {
    int i = blockIdx.x * blockDim.x + threadIdx.x;
    if (i < n4) out[i] = make_float4(0.f, 0.f, 0.f, 0.f);
}

// ---------------------------------------------------------------------------
// Launch #4: W2 transpose to [n][k] fp16
// ---------------------------------------------------------------------------
__global__ void prep_w2t(const float* __restrict__ W2) {
    int idx = blockIdx.x * 256 + threadIdx.x;
    if (idx < COUT * HDIM) {
        int n = idx >> 8, k = idx & 255;
        g_W2h[idx] = __float2half_rn(W2[k * COUT + n]);
    }
}

// ---------------------------------------------------------------------------
// Launch #5: fused prep + node GEMM on fp16 tensor cores.
// Block tile: 64 rows x 64 cols. Builds its own BN-folded fp16 weight slice
// [64 cols][128 k] + bias, converts x rows to fp16, then mma.
// ---------------------------------------------------------------------------
#define XS 136   // half stride for xs/wt rows: (136*2/4)%32 == 4 banks shift -> conflict-free ldsm

__global__ __launch_bounds__(256) void gemm_fused_kernel(
    const float* __restrict__ x,
    const float* __restrict__ gamma, const float* __restrict__ beta,
    const float* __restrict__ mean, const float* __restrict__ var,
    const float* __restrict__ W1, const float* __restrict__ b1) {
    __shared__ float s_sh[CIN], t_sh[CIN];
    __shared__ float dvp[4 * 64];
    __shared__ float dv_s[64];
    __shared__ __half xs[64 * XS];   // [m][k] fp16
    __shared__ __half wt[64 * XS];   // [n][k] fp16 (BN-folded combined weight slice)

    const int tid = threadIdx.x;
    const int m0 = blockIdx.x * 64, n0 = blockIdx.y * 64;

    if (tid < CIN) {
        float s = gamma[tid] * rsqrtf(var[tid] + BN_EPS);
        s_sh[tid] = s;
        t_sh[tid] = beta[tid] - mean[tid] * s;
    }
    __syncthreads();

    // Build fp16 weight slice [jj][k] + bias partials
    {
        int jj = tid & 63;
        int kg = tid >> 6;              // 0..3
        int j = n0 + jj;
        float dacc = 0.f;
        #pragma unroll 4
        for (int k = kg * 32; k < kg * 32 + 32; ++k) {
            float wc;
            if (j < HDIM) wc = W1[k * HDIM + j] - W1[(k + CIN) * HDIM + j];
            else          wc = W1[(k + CIN) * HDIM + (j - HDIM)];
            wt[jj * XS + k] = __float2half_rn(s_sh[k] * wc);
            dacc += t_sh[k] * wc;
        }
        dvp[kg * 64 + jj] = dacc;
    }

    // Load x tile -> fp16 xs (row = tid>>2, k-quarter = tid&3)
    {
        int row = tid >> 2, q = tid & 3;
        bool ok = (m0 + row) < NNODES;
        const float* xr = x + (m0 + row) * CIN + q * 32;
        #pragma unroll
        for (int i = 0; i < 8; ++i) {
            float4 v = ok ? *(const float4*)(xr + i * 4) : make_float4(0.f, 0.f, 0.f, 0.f);
            __half2 h0 = __floats2half2_rn(v.x, v.y);
            __half2 h1 = __floats2half2_rn(v.z, v.w);
            uint2 o;
            o.x = *(uint32_t*)&h0;
            o.y = *(uint32_t*)&h1;
            *(uint2*)&xs[row * XS + q * 32 + i * 4] = o;
        }
    }
    __syncthreads();

    if (tid < 64) {
        int j = n0 + tid;
        dv_s[tid] = dvp[tid] + dvp[64 + tid] + dvp[128 + tid] + dvp[192 + tid]
                  + ((j < HDIM) ? b1[j] : 0.f);
    }

    // mma phase: warp = wm(32 rows) x wn(16 cols)
    const int lane = tid & 31;
    const int w    = tid >> 5;
    const int wm   = w & 1;
    const int wn   = w >> 1;            // 0..3 (16 cols each)
    const int g    = lane >> 2;
    const int tg   = lane & 3;
    const int mat  = lane >> 3, r8 = lane & 7;

    const uint32_t xs_addr = (uint32_t)__cvta_generic_to_shared(xs);
    const uint32_t wt_addr = (uint32_t)__cvta_generic_to_shared(wt);
    uint32_t aBase[2];
    #pragma unroll
    for (int mt = 0; mt < 2; ++mt) {
        int row = wm * 32 + mt * 16 + (mat & 1) * 8 + r8;
        aBase[mt] = xs_addr + (row * XS + (mat >> 1) * 8) * 2;
    }
    const uint32_t bBase = wt_addr + ((wn * 16 + (mat >> 1) * 8 + r8) * XS + (mat & 1) * 8) * 2;

    float acc[2][2][4];
    #pragma unroll
    for (int mt = 0; mt < 2; ++mt)
        #pragma unroll
        for (int nt = 0; nt < 2; ++nt)
            #pragma unroll
            for (int i = 0; i < 4; ++i) acc[mt][nt][i] = 0.f;

    #pragma unroll
    for (int ks = 0; ks < CIN / 16; ++ks) {
        uint32_t kb = ks * 32;
        uint32_t a[2][4];
        #pragma unroll
        for (int mt = 0; mt < 2; ++mt)
            ldsm_x4(a[mt][0], a[mt][1], a[mt][2], a[mt][3], aBase[mt] + kb);
        uint32_t b[2][2];
        ldsm_x4(b[0][0], b[0][1], b[1][0], b[1][1], bBase + kb);
        #pragma unroll
        for (int mt = 0; mt < 2; ++mt)
            #pragma unroll
            for (int nt = 0; nt < 2; ++nt)
                mma_f16(acc[mt][nt][0], acc[mt][nt][1], acc[mt][nt][2], acc[mt][nt][3],
                        a[mt][0], a[mt][1], a[mt][2], a[mt][3],
                        b[nt][0], b[nt][1]);
    }
    __syncthreads();   // dv_s visible to all

    // Epilogue: +bias, fp16 pair stores
    #pragma unroll
    for (int mt = 0; mt < 2; ++mt) {
        #pragma unroll
        for (int nt = 0; nt < 2; ++nt) {
            int lc = wn * 16 + nt * 8 + tg * 2;
            float d0 = dv_s[lc], d1 = dv_s[lc + 1];
            #pragma unroll
            for (int r = 0; r < 2; ++r) {
                int row = m0 + wm * 32 + mt * 16 + g + r * 8;
                if (row < NNODES) {
                    __half2 h = __floats2half2_rn(acc[mt][nt][2 * r] + d0,
                                                  acc[mt][nt][2 * r + 1] + d1);
                    *(uint32_t*)&g_ABh[row * 512 + n0 + lc] = *(uint32_t*)&h;
                }
            }
        }
    }
}

// ---------------------------------------------------------------------------
// Launch #6: persistent edge kernel (fp16 gather + ldmatrix + fp16 mma)
// ---------------------------------------------------------------------------
#define TILE_E 64
#define KS 264
#define NTILES (NEDGES / TILE_E)    // 10000

#define SMEM_W2_HALVES (COUT * KS)
#define SMEM_H_HALVES  (TILE_E * KS)
#define SMEM_BYTES ((SMEM_W2_HALVES + SMEM_H_HALVES) * 2 + COUT * 4)

__global__ __launch_bounds__(256, 2) void edge_kernel(const float* __restrict__ b2,
                                                      int* __restrict__ outI) {
    extern __shared__ __half smem[];
    __half* W2_s = smem;                          // [128][KS]
    __half* h_s  = W2_s + SMEM_W2_HALVES;         // [64][KS]
    float*  b2_s = (float*)(h_s + SMEM_H_HALVES); // [128]

    const int tid  = threadIdx.x;
    const int lane = tid & 31;
    const int w    = tid >> 5;
    const int wm   = w & 1;
    const int wn   = w >> 1;
    const int g    = lane >> 2;
    const int tg   = lane & 3;

    for (int idx = tid; idx < COUT * HDIM / 8; idx += 256) {
        int n = idx >> 5, kc = (idx & 31) * 8;
        *(uint4*)&W2_s[n * KS + kc] = *(const uint4*)&g_W2h[n * HDIM + kc];
    }
    if (tid < COUT) b2_s[tid] = b2[tid];
    __syncthreads();

    const uint32_t h_addr  = (uint32_t)__cvta_generic_to_shared(h_s);
    const uint32_t w2_addr = (uint32_t)__cvta_generic_to_shared(W2_s);
    const int mat = lane >> 3, r8 = lane & 7;
    uint32_t aBase[2], bBase[2];
    #pragma unroll
    for (int mt = 0; mt < 2; ++mt) {
        int row = wm * 32 + mt * 16 + (mat & 1) * 8 + r8;
        aBase[mt] = h_addr + (row * KS + (mat >> 1) * 8) * 2;
    }
    #pragma unroll
    for (int p = 0; p < 2; ++p) {
        int n = wn * 32 + p * 16 + (mat >> 1) * 8 + r8;
        bBase[p] = w2_addr + (n * KS + (mat & 1) * 8) * 2;
    }

    const int kc8 = lane * 8;

    for (int tile = blockIdx.x; tile < NTILES; tile += gridDim.x) {
        const int ebase = tile * TILE_E;

        // Stage 1: gather + relu -> h_s (warp = one row per pass)
        const __half2 z2 = __float2half2_rn(0.f);
        #pragma unroll
        for (int pass = 0; pass < 8; ++pass) {
            int row = pass * 8 + w;
            int d = __ldg(&g_dst[ebase + row]);
            int s = __ldg(&g_src[ebase + row]);
            uint4 ua = *(const uint4*)&g_ABh[d * 512 + kc8];
            uint4 ub = *(const uint4*)&g_ABh[s * 512 + 256 + kc8];
            uint4 o;
            __half2 h;
            h = __hmax2(__hadd2(*(__half2*)&ua.x, *(__half2*)&ub.x), z2); o.x = *(uint32_t*)&h;
            h = __hmax2(__hadd2(*(__half2*)&ua.y, *(__half2*)&ub.y), z2); o.y = *(uint32_t*)&h;
            h = __hmax2(__hadd2(*(__half2*)&ua.z, *(__half2*)&ub.z), z2); o.z = *(uint32_t*)&h;
            h = __hmax2(__hadd2(*(__half2*)&ua.w, *(__half2*)&ub.w), z2); o.w = *(uint32_t*)&h;
            *(uint4*)&h_s[row * KS + kc8] = o;
        }
        __syncthreads();

        // Stage 2: fp16 mma [64x256] @ [256x128]
        float acc[2][4][4];
        #pragma unroll
        for (int mt = 0; mt < 2; ++mt)
            #pragma unroll
            for (int nt = 0; nt < 4; ++nt)
                #pragma unroll
                for (int i = 0; i < 4; ++i) acc[mt][nt][i] = 0.f;

        #pragma unroll 4
        for (int ks = 0; ks < HDIM / 16; ++ks) {
            uint32_t kb = ks * 32;
            uint32_t a[2][4];
            #pragma unroll
            for (int mt = 0; mt < 2; ++mt)
                ldsm_x4(a[mt][0], a[mt][1], a[mt][2], a[mt][3], aBase[mt] + kb);
            uint32_t b[4][2];
            ldsm_x4(b[0][0], b[0][1], b[1][0], b[1][1], bBase[0] + kb);
            ldsm_x4(b[2][0], b[2][1], b[3][0], b[3][1], bBase[1] + kb);
            #pragma unroll
            for (int mt = 0; mt < 2; ++mt)
                #pragma unroll
                for (int nt = 0; nt < 4; ++nt)
                    mma_f16(acc[mt][nt][0], acc[mt][nt][1], acc[mt][nt][2], acc[mt][nt][3],
                            a[mt][0], a[mt][1], a[mt][2], a[mt][3],
                            b[nt][0], b[nt][1]);
        }
        __syncthreads();

        // Epilogue: +b2, predicated positive-only int atomicMax
        int drow[2][2];
        #pragma unroll
        for (int mt = 0; mt < 2; ++mt)
            #pragma unroll
            for (int r = 0; r < 2; ++r)
                drow[mt][r] = __ldg(&g_dst[ebase + wm * 32 + mt * 16 + g + r * 8]);

        #pragma unroll
        for (int mt = 0; mt < 2; ++mt) {
            #pragma unroll
            for (int nt = 0; nt < 4; ++nt) {
                #pragma unroll
                for (int i = 0; i < 4; ++i) {
                    int col = wn * 32 + nt * 8 + tg * 2 + (i & 1);
                    float v = acc[mt][nt][i] + b2_s[col];
                    if (v > 0.f) {
                        atomicMax(outI + drow[mt][i >> 1] * COUT + col, __float_as_int(v));
                    }
                }
            }
        }
    }
}

// ---------------------------------------------------------------------------
// Launch — exactly 6 kernels
// ---------------------------------------------------------------------------
extern "C" void kernel_launch(void* const* d_in, const int* in_sizes, int n_in,
                              void* d_out, int out_size) {
    const float* x        = (const float*)d_in[0];
    const int*   eiw      = (const int*)d_in[1];
    const float* bn_gamma = (const float*)d_in[2];
    const float* bn_beta  = (const float*)d_in[3];
    const float* bn_mean  = (const float*)d_in[4];
    const float* bn_var   = (const float*)d_in[5];
    const float* W1       = (const float*)d_in[6];
    const float* b1       = (const float*)d_in[7];
    const float* W2       = (const float*)d_in[8];
    const float* b2       = (const float*)d_in[9];

    cudaFuncSetAttribute(edge_kernel, cudaFuncAttributeMaxDynamicSharedMemorySize, SMEM_BYTES);

    detect_kernel<<<1, 256>>>(eiw);                                            // 1
    extract_kernel<<<(NEDGES + 255) / 256, 256>>>(eiw);                        // 2
    zero_kernel<<<(NNODES * COUT / 4 + 255) / 256, 256>>>((float4*)d_out,
                                                          NNODES * COUT / 4);  // 3
    prep_w2t<<<128, 256>>>(W2);                                                // 4
    dim3 g1((NNODES + 63) / 64, 512 / 64);
    gemm_fused_kernel<<<g1, 256>>>(x, bn_gamma, bn_beta, bn_mean, bn_var, W1, b1); // 5
    edge_kernel<<<304, 256, SMEM_BYTES>>>(b2, (int*)d_out);                    // 6
}

// round 9
// speedup vs baseline: 1.5643x; 1.1059x over previous
#include <cuda_runtime.h>
#include <cuda_fp16.h>
#include <cstdint>

// Problem constants (fixed shapes)
#define NNODES 10000
#define NEDGES 640000
#define CIN    128
#define COUT   128
#define HDIM   256
#define BN_EPS 1e-5f

// ---------------------------------------------------------------------------
// Scratch (__device__ globals; no allocation allowed)
// ---------------------------------------------------------------------------
__device__ __align__(16) __half g_ABh[NNODES * 512];  // [n][0:256]=A' (dst), [n][256:512]=B (src)
__device__ __align__(16) __half g_W2h[COUT * HDIM];   // W2^T [n][k], fp16
__device__ int    g_src[NEDGES];
__device__ int    g_dst[NEDGES];

// ---------------------------------------------------------------------------
// fp16 mma m16n8k16 (fp32 accumulate) + ldmatrix helpers
// ---------------------------------------------------------------------------
__device__ __forceinline__ void mma_f16(float& c0, float& c1, float& c2, float& c3,
                                        uint32_t a0, uint32_t a1, uint32_t a2, uint32_t a3,
                                        uint32_t b0, uint32_t b1) {
    asm volatile(
        "mma.sync.aligned.m16n8k16.row.col.f32.f16.f16.f32 "
        "{%0,%1,%2,%3}, {%4,%5,%6,%7}, {%8,%9}, {%0,%1,%2,%3};\n"
        : "+f"(c0), "+f"(c1), "+f"(c2), "+f"(c3)
        : "r"(a0), "r"(a1), "r"(a2), "r"(a3), "r"(b0), "r"(b1));
}

__device__ __forceinline__ void ldsm_x4(uint32_t& r0, uint32_t& r1, uint32_t& r2, uint32_t& r3,
                                        uint32_t addr) {
    asm volatile("ldmatrix.sync.aligned.m8n8.x4.shared.b16 {%0,%1,%2,%3}, [%4];"
                 : "=r"(r0), "=r"(r1), "=r"(r2), "=r"(r3) : "r"(addr));
}

// ---------------------------------------------------------------------------
// Launch #1: fused detect + extract + zero-output.
// Per-block dtype detection: ORs this block's odd 32-bit words; all-zero over
// 256 edges is impossible for int32 node indices (P ~ 1e-1024) and guaranteed
// for int64 values < 10000, so every block reaches the same verdict.
// ---------------------------------------------------------------------------
__global__ void extract_fused_kernel(const int* __restrict__ w, float4* __restrict__ out4) {
    __shared__ int sacc;
    const int tid = threadIdx.x;
    const int i = blockIdx.x * 256 + tid;
    if (tid == 0) sacc = 0;
    __syncthreads();
    int v = (i < NEDGES) ? w[2 * i + 1] : 0;
    if (__syncthreads_or(v != 0)) v = 1; else v = 0;   // block-wide OR
    const int is64 = (v == 0);

    if (i < NNODES * COUT / 4) out4[i] = make_float4(0.f, 0.f, 0.f, 0.f);

    if (i >= NEDGES) return;
    int s, d;
    if (is64) {
        s = w[2 * i];
        d = w[2 * (NEDGES + i)];
    } else {
        s = w[i];
        d = w[NEDGES + i];
    }
    g_src[i] = min(max(s, 0), NNODES - 1);
    g_dst[i] = min(max(d, 0), NNODES - 1);
}

// ---------------------------------------------------------------------------
// Launch #2: fused prep + node GEMM on fp16 tensor cores (unchanged from R8)
// ---------------------------------------------------------------------------
#define XS 136

__global__ __launch_bounds__(256) void gemm_fused_kernel(
    const float* __restrict__ x,
    const float* __restrict__ gamma, const float* __restrict__ beta,
    const float* __restrict__ mean, const float* __restrict__ var,
    const float* __restrict__ W1, const float* __restrict__ b1) {
    __shared__ float s_sh[CIN], t_sh[CIN];
    __shared__ float dvp[4 * 64];
    __shared__ float dv_s[64];
    __shared__ __half xs[64 * XS];
    __shared__ __half wt[64 * XS];

    const int tid = threadIdx.x;
    const int m0 = blockIdx.x * 64, n0 = blockIdx.y * 64;

    if (tid < CIN) {
        float s = gamma[tid] * rsqrtf(var[tid] + BN_EPS);
        s_sh[tid] = s;
        t_sh[tid] = beta[tid] - mean[tid] * s;
    }
    __syncthreads();

    {
        int jj = tid & 63;
        int kg = tid >> 6;
        int j = n0 + jj;
        float dacc = 0.f;
        #pragma unroll 4
        for (int k = kg * 32; k < kg * 32 + 32; ++k) {
            float wc;
            if (j < HDIM) wc = W1[k * HDIM + j] - W1[(k + CIN) * HDIM + j];
            else          wc = W1[(k + CIN) * HDIM + (j - HDIM)];
            wt[jj * XS + k] = __float2half_rn(s_sh[k] * wc);
            dacc += t_sh[k] * wc;
        }
        dvp[kg * 64 + jj] = dacc;
    }

    {
        int row = tid >> 2, q = tid & 3;
        bool ok = (m0 + row) < NNODES;
        const float* xr = x + (m0 + row) * CIN + q * 32;
        #pragma unroll
        for (int i = 0; i < 8; ++i) {
            float4 v = ok ? *(const float4*)(xr + i * 4) : make_float4(0.f, 0.f, 0.f, 0.f);
            __half2 h0 = __floats2half2_rn(v.x, v.y);
            __half2 h1 = __floats2half2_rn(v.z, v.w);
            uint2 o;
            o.x = *(uint32_t*)&h0;
            o.y = *(uint32_t*)&h1;
            *(uint2*)&xs[row * XS + q * 32 + i * 4] = o;
        }
    }
    __syncthreads();

    if (tid < 64) {
        int j = n0 + tid;
        dv_s[tid] = dvp[tid] + dvp[64 + tid] + dvp[128 + tid] + dvp[192 + tid]
                  + ((j < HDIM) ? b1[j] : 0.f);
    }

    const int lane = tid & 31;
    const int w    = tid >> 5;
    const int wm   = w & 1;
    const int wn   = w >> 1;
    const int g    = lane >> 2;
    const int tg   = lane & 3;
    const int mat  = lane >> 3, r8 = lane & 7;

    const uint32_t xs_addr = (uint32_t)__cvta_generic_to_shared(xs);
    const uint32_t wt_addr = (uint32_t)__cvta_generic_to_shared(wt);
    uint32_t aBase[2];
    #pragma unroll
    for (int mt = 0; mt < 2; ++mt) {
        int row = wm * 32 + mt * 16 + (mat & 1) * 8 + r8;
        aBase[mt] = xs_addr + (row * XS + (mat >> 1) * 8) * 2;
    }
    const uint32_t bBase = wt_addr + ((wn * 16 + (mat >> 1) * 8 + r8) * XS + (mat & 1) * 8) * 2;

    float acc[2][2][4];
    #pragma unroll
    for (int mt = 0; mt < 2; ++mt)
        #pragma unroll
        for (int nt = 0; nt < 2; ++nt)
            #pragma unroll
            for (int i = 0; i < 4; ++i) acc[mt][nt][i] = 0.f;

    #pragma unroll
    for (int ks = 0; ks < CIN / 16; ++ks) {
        uint32_t kb = ks * 32;
        uint32_t a[2][4];
        #pragma unroll
        for (int mt = 0; mt < 2; ++mt)
            ldsm_x4(a[mt][0], a[mt][1], a[mt][2], a[mt][3], aBase[mt] + kb);
        uint32_t b[2][2];
        ldsm_x4(b[0][0], b[0][1], b[1][0], b[1][1], bBase + kb);
        #pragma unroll
        for (int mt = 0; mt < 2; ++mt)
            #pragma unroll
            for (int nt = 0; nt < 2; ++nt)
                mma_f16(acc[mt][nt][0], acc[mt][nt][1], acc[mt][nt][2], acc[mt][nt][3],
                        a[mt][0], a[mt][1], a[mt][2], a[mt][3],
                        b[nt][0], b[nt][1]);
    }
    __syncthreads();

    #pragma unroll
    for (int mt = 0; mt < 2; ++mt) {
        #pragma unroll
        for (int nt = 0; nt < 2; ++nt) {
            int lc = wn * 16 + nt * 8 + tg * 2;
            float d0 = dv_s[lc], d1 = dv_s[lc + 1];
            #pragma unroll
            for (int r = 0; r < 2; ++r) {
                int row = m0 + wm * 32 + mt * 16 + g + r * 8;
                if (row < NNODES) {
                    __half2 h = __floats2half2_rn(acc[mt][nt][2 * r] + d0,
                                                  acc[mt][nt][2 * r + 1] + d1);
                    *(uint32_t*)&g_ABh[row * 512 + n0 + lc] = *(uint32_t*)&h;
                }
            }
        }
    }
}

// ---------------------------------------------------------------------------
// Launch #3: W2 transpose to [n][k] fp16
// ---------------------------------------------------------------------------
__global__ void prep_w2t(const float* __restrict__ W2) {
    int idx = blockIdx.x * 256 + threadIdx.x;
    if (idx < COUT * HDIM) {
        int n = idx >> 8, k = idx & 255;
        g_W2h[idx] = __float2half_rn(W2[k * COUT + n]);
    }
}

// ---------------------------------------------------------------------------
// Launch #4: persistent edge kernel. 512 threads/CTA, 1 CTA/SM, two
// independent 8-warp groups on separate 128-edge tiles & h buffers, shared W2.
// Warp tile 32x64 (intensity 21.3 vs 16), named barriers per group.
// ---------------------------------------------------------------------------
#define TILE_E 128
#define KS 264                        // half stride per row; %128B phase 4 banks -> conflict-free
#define NT128 (NEDGES / TILE_E)       // 5000

#define W2_HALVES (COUT * KS)         // 33792
#define H_HALVES  (TILE_E * KS)       // 33792
#define SMEM_BYTES ((W2_HALVES + 2 * H_HALVES) * 2 + COUT * 4)   // 203264 B

__global__ __launch_bounds__(512, 1) void edge_kernel(const float* __restrict__ b2,
                                                      int* __restrict__ outI) {
    extern __shared__ __half smem[];
    __half* W2_s = smem;                          // [128][KS]
    __half* hb0  = smem + W2_HALVES;              // [128][KS]
    __half* hb1  = hb0 + H_HALVES;                // [128][KS]
    float*  b2_s = (float*)(hb1 + H_HALVES);      // [128]

    const int tid  = threadIdx.x;
    const int lane = tid & 31;
    const int w    = tid >> 5;        // 0..15
    const int grp  = w >> 3;          // group 0/1
    const int ww   = w & 7;           // warp within group
    const int wm   = ww & 3;          // row band (32 rows)
    const int wn   = ww >> 2;         // col band (64 cols)
    const int gg   = lane >> 2;
    const int tg   = lane & 3;

    // W2^T into smem once (512 threads)
    for (int idx = tid; idx < COUT * HDIM / 8; idx += 512) {
        int n = idx >> 5, kc = (idx & 31) * 8;
        *(uint4*)&W2_s[n * KS + kc] = *(const uint4*)&g_W2h[n * HDIM + kc];
    }
    if (tid < COUT) b2_s[tid] = b2[tid];
    __syncthreads();

    __half* hb = grp ? hb1 : hb0;
    const uint32_t h_addr  = (uint32_t)__cvta_generic_to_shared(hb);
    const uint32_t w2_addr = (uint32_t)__cvta_generic_to_shared(W2_s);
    const int mat = lane >> 3, r8 = lane & 7;
    uint32_t aBase[2];
    #pragma unroll
    for (int mt = 0; mt < 2; ++mt) {
        int row = wm * 32 + mt * 16 + (mat & 1) * 8 + r8;
        aBase[mt] = h_addr + (row * KS + (mat >> 1) * 8) * 2;
    }
    uint32_t bBase[4];
    #pragma unroll
    for (int p = 0; p < 4; ++p) {
        int n = wn * 64 + p * 16 + (mat >> 1) * 8 + r8;
        bBase[p] = w2_addr + (n * KS + (mat & 1) * 8) * 2;
    }

    const int kc8 = lane * 8;
    const int barid = grp + 1;

    for (int tile = blockIdx.x * 2 + grp; tile < NT128; tile += gridDim.x * 2) {
        const int ebase = tile * TILE_E;

        // Stage 1: gather + relu -> hb (warp = one row per pass, 16 passes)
        const __half2 z2 = __float2half2_rn(0.f);
        #pragma unroll
        for (int pass = 0; pass < 16; ++pass) {
            int row = pass * 8 + ww;
            int d = __ldg(&g_dst[ebase + row]);
            int s = __ldg(&g_src[ebase + row]);
            uint4 ua = *(const uint4*)&g_ABh[d * 512 + kc8];
            uint4 ub = *(const uint4*)&g_ABh[s * 512 + 256 + kc8];
            uint4 o;
            __half2 h;
            h = __hmax2(__hadd2(*(__half2*)&ua.x, *(__half2*)&ub.x), z2); o.x = *(uint32_t*)&h;
            h = __hmax2(__hadd2(*(__half2*)&ua.y, *(__half2*)&ub.y), z2); o.y = *(uint32_t*)&h;
            h = __hmax2(__hadd2(*(__half2*)&ua.z, *(__half2*)&ub.z), z2); o.z = *(uint32_t*)&h;
            h = __hmax2(__hadd2(*(__half2*)&ua.w, *(__half2*)&ub.w), z2); o.w = *(uint32_t*)&h;
            *(uint4*)&hb[row * KS + kc8] = o;
        }
        asm volatile("bar.sync %0, 256;" :: "r"(barid) : "memory");

        // Stage 2: fp16 mma, warp tile 32x64, [128x256] @ [256x128]
        float acc[2][8][4];
        #pragma unroll
        for (int mt = 0; mt < 2; ++mt)
            #pragma unroll
            for (int nt = 0; nt < 8; ++nt)
                #pragma unroll
                for (int i = 0; i < 4; ++i) acc[mt][nt][i] = 0.f;

        #pragma unroll 4
        for (int ks = 0; ks < HDIM / 16; ++ks) {
            uint32_t kb = ks * 32;
            uint32_t a[2][4];
            #pragma unroll
            for (int mt = 0; mt < 2; ++mt)
                ldsm_x4(a[mt][0], a[mt][1], a[mt][2], a[mt][3], aBase[mt] + kb);
            uint32_t b[8][2];
            #pragma unroll
            for (int p = 0; p < 4; ++p)
                ldsm_x4(b[2 * p][0], b[2 * p][1], b[2 * p + 1][0], b[2 * p + 1][1],
                        bBase[p] + kb);
            #pragma unroll
            for (int mt = 0; mt < 2; ++mt)
                #pragma unroll
                for (int nt = 0; nt < 8; ++nt)
                    mma_f16(acc[mt][nt][0], acc[mt][nt][1], acc[mt][nt][2], acc[mt][nt][3],
                            a[mt][0], a[mt][1], a[mt][2], a[mt][3],
                            b[nt][0], b[nt][1]);
        }
        asm volatile("bar.sync %0, 256;" :: "r"(barid) : "memory");

        // Epilogue: +b2, predicated positive-only int atomicMax
        int drow[2][2];
        #pragma unroll
        for (int mt = 0; mt < 2; ++mt)
            #pragma unroll
            for (int r = 0; r < 2; ++r)
                drow[mt][r] = __ldg(&g_dst[ebase + wm * 32 + mt * 16 + gg + r * 8]);

        #pragma unroll
        for (int mt = 0; mt < 2; ++mt) {
            #pragma unroll
            for (int nt = 0; nt < 8; ++nt) {
                #pragma unroll
                for (int i = 0; i < 4; ++i) {
                    int col = wn * 64 + nt * 8 + tg * 2 + (i & 1);
                    float v = acc[mt][nt][i] + b2_s[col];
                    if (v > 0.f) {
                        atomicMax(outI + drow[mt][i >> 1] * COUT + col, __float_as_int(v));
                    }
                }
            }
        }
    }
}

// ---------------------------------------------------------------------------
// Launch — exactly 4 kernels; edge_kernel is #4 (the one ncu profiles)
// ---------------------------------------------------------------------------
extern "C" void kernel_launch(void* const* d_in, const int* in_sizes, int n_in,
                              void* d_out, int out_size) {
    const float* x        = (const float*)d_in[0];
    const int*   eiw      = (const int*)d_in[1];
    const float* bn_gamma = (const float*)d_in[2];
    const float* bn_beta  = (const float*)d_in[3];
    const float* bn_mean  = (const float*)d_in[4];
    const float* bn_var   = (const float*)d_in[5];
    const float* W1       = (const float*)d_in[6];
    const float* b1       = (const float*)d_in[7];
    const float* W2       = (const float*)d_in[8];
    const float* b2       = (const float*)d_in[9];

    cudaFuncSetAttribute(edge_kernel, cudaFuncAttributeMaxDynamicSharedMemorySize, SMEM_BYTES);

    extract_fused_kernel<<<(NEDGES + 255) / 256, 256>>>(eiw, (float4*)d_out);      // 1
    dim3 g1((NNODES + 63) / 64, 512 / 64);
    gemm_fused_kernel<<<g1, 256>>>(x, bn_gamma, bn_beta, bn_mean, bn_var, W1, b1); // 2
    prep_w2t<<<128, 256>>>(W2);                                                    // 3
    edge_kernel<<<152, 512, SMEM_BYTES>>>(b2, (int*)d_out);                        // 4
}